// round 13
// baseline (speedup 1.0000x reference)
#include <cuda_runtime.h>
#include <math.h>

#define NN 2048
#define CC 384
#define HH 16
#define DD 24
#define L2E 1.44269504088896340736f
#define WSZ (CC*CC)

// Scratch (allocation-free rule: __device__ globals)
__device__ unsigned g_xnh[NN*CC], g_xnl[NN*CC];      // tf32 hi/lo of layernormed x
__device__ unsigned g_wh[5*WSZ], g_wl[5*WSZ];        // tf32 hi/lo of wq,wk,wv,wg,wo
__device__ unsigned g_q[NN*CC];                      // [H][N][D], *D^-0.5*log2e, tf32
// K pair-interleaved: [H][12 rows=(j*4+t)][2N], element (n,e) = K[d=8j+t+4e][key n]
__device__ unsigned g_kT2[CC*NN];
// V pair-interleaved: [H][64 tiles][16 rows=(j*4+t)][48=(d*2+e)],
//   element = V[key=32T+8j+t+4e][d]
__device__ unsigned g_v2[CC*NN];
__device__ float    g_gate[NN*CC];                   // sigmoid(xn@wg.T), [N][C]
__device__ unsigned g_gatedh[NN*CC], g_gatedl[NN*CC];// tf32 hi/lo of wa*gate
__device__ float    g_biask[NN];                     // 1e9*(mask-1)*log2e

// ---------------------------------------------------------------------------
__device__ __forceinline__ unsigned cvt_tf32(float x){
  unsigned r; asm("cvt.rna.tf32.f32 %0, %1;" : "=r"(r) : "f"(x)); return r;
}
__device__ __forceinline__ void mma_tf32(float c[4], const unsigned a[4],
                                         unsigned b0, unsigned b1){
  asm volatile("mma.sync.aligned.m16n8k8.row.col.f32.tf32.tf32.f32 "
    "{%0,%1,%2,%3}, {%4,%5,%6,%7}, {%8,%9}, {%0,%1,%2,%3};"
    : "+f"(c[0]),"+f"(c[1]),"+f"(c[2]),"+f"(c[3])
    : "r"(a[0]),"r"(a[1]),"r"(a[2]),"r"(a[3]), "r"(b0),"r"(b1));
}
__device__ __forceinline__ void cp16(void* dst, const void* src){
  unsigned d = (unsigned)__cvta_generic_to_shared(dst);
  asm volatile("cp.async.cg.shared.global [%0], [%1], 16;\n" :: "r"(d), "l"(src));
}
__device__ __forceinline__ void cp_commit(){ asm volatile("cp.async.commit_group;\n"::); }
__device__ __forceinline__ void cp_wait0(){ asm volatile("cp.async.wait_group 0;\n"::); }

// ---------------------------------------------------------------------------
// LayerNorm -> tf32 hi/lo; also key bias (log2 domain).
// ---------------------------------------------------------------------------
__global__ __launch_bounds__(128) void ln_kernel(
    const float* __restrict__ x, const float* __restrict__ mask,
    const float* __restrict__ ln_w, const float* __restrict__ ln_b) {
  int row = blockIdx.x, tid = threadIdx.x;
  const float* xr = x + row*CC;
  float v[3]; float s = 0.f;
  #pragma unroll
  for (int i=0;i<3;i++){ v[i]=xr[tid+128*i]; s+=v[i]; }
  __shared__ float red[4];
  #pragma unroll
  for (int o=16;o;o>>=1) s += __shfl_xor_sync(~0u,s,o);
  if ((tid&31)==0) red[tid>>5]=s;
  __syncthreads();
  float mu = (red[0]+red[1]+red[2]+red[3])*(1.f/CC);
  __syncthreads();
  float sq=0.f;
  #pragma unroll
  for (int i=0;i<3;i++){ float d=v[i]-mu; sq+=d*d; }
  #pragma unroll
  for (int o=16;o;o>>=1) sq += __shfl_xor_sync(~0u,sq,o);
  if ((tid&31)==0) red[tid>>5]=sq;
  __syncthreads();
  float var = (red[0]+red[1]+red[2]+red[3])*(1.f/CC);
  float rs = rsqrtf(var + 1e-5f);
  #pragma unroll
  for (int i=0;i<3;i++){
    int c = tid+128*i;
    float y = (v[i]-mu)*rs*ln_w[c] + ln_b[c];
    unsigned h = cvt_tf32(y);
    g_xnh[row*CC+c] = h;
    g_xnl[row*CC+c] = cvt_tf32(y - __uint_as_float(h));
  }
  if (tid==0) g_biask[row] = 1e9f*(mask[row]-1.f)*L2E;
}

// ---------------------------------------------------------------------------
// Split the 5 weight matrices into tf32 hi/lo (order: q,k,v,g,o).
// ---------------------------------------------------------------------------
__global__ __launch_bounds__(256) void wconv_kernel(
    const float* __restrict__ wq, const float* __restrict__ wk,
    const float* __restrict__ wv, const float* __restrict__ wg,
    const float* __restrict__ wo) {
  int which = blockIdx.y;
  const float* w = (which==0)?wq:(which==1)?wk:(which==2)?wv:(which==3)?wg:wo;
  int i = blockIdx.x*256 + threadIdx.x;
  float v = w[i];
  unsigned h = cvt_tf32(v);
  g_wh[which*WSZ + i] = h;
  g_wl[which*WSZ + i] = cvt_tf32(v - __uint_as_float(h));
}

// ---------------------------------------------------------------------------
// 3xTF32 tensor-core GEMM, 64x64 tile, K=384, cp.async double-buffered.
// ---------------------------------------------------------------------------
__device__ __forceinline__ void gemm_tc(const unsigned* __restrict__ pAh,
                                        const unsigned* __restrict__ pAl,
                                        const unsigned* __restrict__ pBh,
                                        const unsigned* __restrict__ pBl,
                                        int n0, int c0, float acc[4][4],
                                        unsigned* sm) {
  int tid = threadIdx.x;
  int lane = tid&31, w = tid>>5;
  int wm = w>>1, wn = w&1;
  int g = lane>>2, tg = lane&3;
  int r0 = wm*16 + g, r1 = r0 + 8;

  auto stage = [&](int kt, int b){
    int k0 = kt*32;
    unsigned* base = sm + b*9216;
    #pragma unroll
    for (int i=0;i<8;i++){
      int f = tid + i*256;                 // 0..2047 16B chunks
      int a = f>>9, rr = (f&511)>>3, c4 = (f&7)*4;
      const unsigned* src =
        (a==0) ? &pAh[(n0+rr)*CC + k0 + c4] :
        (a==1) ? &pAl[(n0+rr)*CC + k0 + c4] :
        (a==2) ? &pBh[(c0+rr)*CC + k0 + c4] :
                 &pBl[(c0+rr)*CC + k0 + c4];
      cp16(base + a*2304 + rr*36 + c4, src);
    }
    cp_commit();
  };

  stage(0, 0);
  for (int kt=0; kt<12; kt++){
    int b = kt&1;
    cp_wait0();
    __syncthreads();
    if (kt < 11) stage(kt+1, b^1);
    const unsigned* Ah = sm + b*9216;
    const unsigned* Al = Ah + 2304;
    const unsigned* Bh = Al + 2304;
    const unsigned* Bl = Bh + 2304;
    #pragma unroll
    for (int ks=0; ks<4; ks++){
      int k = ks*8;
      unsigned ah[4], al[4];
      ah[0]=Ah[r0*36+k+tg]; ah[1]=Ah[r1*36+k+tg];
      ah[2]=Ah[r0*36+k+tg+4]; ah[3]=Ah[r1*36+k+tg+4];
      al[0]=Al[r0*36+k+tg]; al[1]=Al[r1*36+k+tg];
      al[2]=Al[r0*36+k+tg+4]; al[3]=Al[r1*36+k+tg+4];
      #pragma unroll
      for (int nn=0; nn<4; nn++){
        int col = wn*32 + 8*nn + g;
        unsigned bh0=Bh[col*36+k+tg], bh1=Bh[col*36+k+tg+4];
        unsigned bl0=Bl[col*36+k+tg], bl1=Bl[col*36+k+tg+4];
        mma_tf32(acc[nn], ah, bh0, bh1);
        mma_tf32(acc[nn], al, bh0, bh1);
        mma_tf32(acc[nn], ah, bl0, bl1);
      }
    }
  }
}

// ---------------------------------------------------------------------------
// All four projections (blockIdx.z selects q/k/v/g).
// q stored tf32 [H][N][D]; k/v stored tf32 in pair-interleaved MMA layouts.
// ---------------------------------------------------------------------------
__device__ __forceinline__ void proj_store(int proj, int row, int col, float val,
                                           const float* __restrict__ bq){
  if (proj==0){
    val = (val + bq[col]) * (0.2041241452f * L2E);   // D^-0.5 * log2e
    g_q[(col/DD)*NN*DD + row*DD + (col%DD)] = cvt_tf32(val);
  } else if (proj==1){
    int h = col/DD, dd = col%DD;
    int j = dd>>3, rem = dd&7, e = rem>>2, t = rem&3;
    g_kT2[h*24*NN + (j*4+t)*2*NN + 2*row + e] = cvt_tf32(val);
  } else if (proj==2){
    int h = col/DD, d = col%DD;
    int T = row>>5, r5 = row&31;
    int j = r5>>3, rem = r5&7, e = rem>>2, t = rem&3;
    g_v2[((h*64 + T)*16 + j*4 + t)*48 + d*2 + e] = cvt_tf32(val);
  } else {
    g_gate[row*CC+col] = 1.f/(1.f+__expf(-val));
  }
}

__global__ __launch_bounds__(256) void proj_kernel(const float* __restrict__ bq) {
  extern __shared__ unsigned smu[];
  int proj = blockIdx.z;
  int c0 = blockIdx.x*64, n0 = blockIdx.y*64;
  float acc[4][4] = {};
  gemm_tc(g_xnh, g_xnl, g_wh + proj*WSZ, g_wl + proj*WSZ, n0, c0, acc, smu);
  int lane = threadIdx.x&31, w = threadIdx.x>>5;
  int wm = w>>1, wn = w&1;
  int g = lane>>2, tg = lane&3;
  int row0 = n0 + wm*16 + g, row1 = row0 + 8;
  #pragma unroll
  for (int nn=0;nn<4;nn++){
    int col = c0 + wn*32 + 8*nn + 2*tg;
    proj_store(proj, row0, col,   acc[nn][0], bq);
    proj_store(proj, row0, col+1, acc[nn][1], bq);
    proj_store(proj, row1, col,   acc[nn][2], bq);
    proj_store(proj, row1, col+1, acc[nn][3], bq);
  }
}

// ---------------------------------------------------------------------------
// Tensor-core flash attention with intra-block key-split.
// 256 threads = 2 warp-groups of 4 warps; group g handles keys [g*1024,(g+1)*1024)
// in 32 tiles of 32 keys, with its OWN 2-stage cp.async pipeline and named
// barrier (no cross-group sync until the final merge).
// Dynamic smem 65536B = 4 buffers (group x stage) of 4096 floats:
//   [0,2304)    pair (stride 36); P overwrites in place
//   [2304,3168) K pair-interleaved (12 rows x 72, LDS.64 B-frags)
//   [3168,4064) V pair-interleaved (16 rows x 56, LDS.64 B-frags)
// Final: group1 parks (m,l,o) in smem; group0 does the exact flash merge,
// applies 1/l + sigmoid gate, emits hi/lo.
// ---------------------------------------------------------------------------
__global__ __launch_bounds__(256,3) void attn_kernel(const float* __restrict__ pair) {
  extern __shared__ float smf[];
  unsigned* smu = (unsigned*)smf;

  int h = blockIdx.y, q0 = blockIdx.x*64;
  int tid = threadIdx.x;
  int grp = tid>>7, t128 = tid&127;
  int w = t128>>5, lane = tid&31;
  int g = lane>>2, tg = lane&3;
  int r0 = 16*w + g, r1 = r0 + 8;
  bool lo64 = (t128 < 64);
  int kz = grp*1024;
  int bufbase = grp*8192;                  // 2 buffers of 4096 floats per group

  // ---- fixed staging slots (computed once; kz folded in) ----
  const float* pb = pair + (size_t)h*NN*NN + (size_t)q0*NN + kz;
  const float* psrc[4]; int pdst[4];
  #pragma unroll
  for (int i=0;i<4;i++){
    int f = t128 + 128*i;                  // 512 chunks: 64 rows x 8
    int r = f>>3, c4 = (f&7)*4;
    psrc[i] = pb + (size_t)r*NN + c4;
    pdst[i] = r*36 + c4;
  }
  const unsigned* kTb2 = g_kT2 + h*24*NN + kz*2;
  int kr0 = t128>>4,       kq0 = t128&15;
  int kr1 = (t128+128)>>4, kq1 = (t128+128)&15;   // rows 8..11, t128<64 only
  const unsigned* ks0 = kTb2 + kr0*2*NN + kq0*4;
  const unsigned* ks1 = kTb2 + kr1*2*NN + kq1*4;
  int kd0 = kr0*72 + kq0*4, kd1 = kr1*72 + kq1*4;

  const unsigned* vb2 = g_v2 + h*64*768 + (kz/32)*768;
  int vr0 = t128/12,       vq0 = t128 - vr0*12;
  int vr1 = (t128+128)/12, vq1 = (t128+128) - vr1*12;  // t128<64 only
  const unsigned* vs0 = vb2 + vr0*48 + vq0*4;
  const unsigned* vs1 = vb2 + vr1*48 + vq1*4;
  int vd0 = vr0*56 + vq0*4, vd1 = vr1*56 + vq1*4;

  auto stage = [&](int t, int s){
    float*    pairb = smf + bufbase + s*4096;
    unsigned* Kb    = smu + bufbase + s*4096 + 2304;
    unsigned* Vb    = smu + bufbase + s*4096 + 3168;
    int koff = t*32;
    #pragma unroll
    for (int i=0;i<4;i++) cp16(pairb + pdst[i], psrc[i] + koff);
    cp16(Kb + kd0, ks0 + t*64);
    if (lo64) cp16(Kb + kd1, ks1 + t*64);
    cp16(Vb + vd0, vs0 + t*768);
    if (lo64) cp16(Vb + vd1, vs1 + t*768);
    cp_commit();
  };

  // Q A-frags in registers (pre-converted tf32)
  unsigned qa[3][4];
  {
    const unsigned* qb = &g_q[(size_t)h*NN*DD + (size_t)q0*DD];
    #pragma unroll
    for (int j=0;j<3;j++){
      qa[j][0] = qb[r0*DD + 8*j+tg];
      qa[j][1] = qb[r1*DD + 8*j+tg];
      qa[j][2] = qb[r0*DD + 8*j+tg+4];
      qa[j][3] = qb[r1*DD + 8*j+tg+4];
    }
  }
  float m0=-1e30f, m1=-1e30f, l0=0.f, l1=0.f;
  float o[3][4] = {};

  stage(0, 0);
  for (int t=0;t<32;t++){
    int s = t&1;
    cp_wait0();
    asm volatile("bar.sync %0, 128;" :: "r"(grp+1) : "memory");
    if (t < 31) stage(t+1, s^1);

    float*          bP = smf + bufbase + s*4096;
    const unsigned* bK = smu + bufbase + s*4096 + 2304;
    const unsigned* bV = smu + bufbase + s*4096 + 3168;
    const float*    bb = &g_biask[kz + t*32];

    // C := pair*log2e + bias (fp32 exact)
    float c[4][4];
    #pragma unroll
    for (int nn=0;nn<4;nn++){
      float2 x0 = *(const float2*)&bP[r0*36 + 8*nn+2*tg];
      float2 x1 = *(const float2*)&bP[r1*36 + 8*nn+2*tg];
      float2 bv = *(const float2*)&bb[8*nn + 2*tg];
      c[nn][0] = fmaf(x0.x, L2E, bv.x);
      c[nn][1] = fmaf(x0.y, L2E, bv.y);
      c[nn][2] = fmaf(x1.x, L2E, bv.x);
      c[nn][3] = fmaf(x1.y, L2E, bv.y);
    }
    // S += Q.K^T  (B-frag pairs via one LDS.64 each)
    #pragma unroll
    for (int j=0;j<3;j++){
      #pragma unroll
      for (int nn=0;nn<4;nn++){
        uint2 kk = *(const uint2*)&bK[(j*4+tg)*72 + (8*nn+g)*2];
        mma_tf32(c[nn], qa[j], kk.x, kk.y);
      }
    }

    // online softmax (log2 domain); P overwrites pair area (warp-private rows)
    float rm0=-1e30f, rm1=-1e30f;
    #pragma unroll
    for (int nn=0;nn<4;nn++){
      rm0 = fmaxf(rm0, fmaxf(c[nn][0], c[nn][1]));
      rm1 = fmaxf(rm1, fmaxf(c[nn][2], c[nn][3]));
    }
    rm0 = fmaxf(rm0, __shfl_xor_sync(~0u,rm0,1));
    rm0 = fmaxf(rm0, __shfl_xor_sync(~0u,rm0,2));
    rm1 = fmaxf(rm1, __shfl_xor_sync(~0u,rm1,1));
    rm1 = fmaxf(rm1, __shfl_xor_sync(~0u,rm1,2));
    float mn0 = fmaxf(m0, rm0), mn1 = fmaxf(m1, rm1);
    float a0 = exp2f(m0-mn0), a1 = exp2f(m1-mn1);
    float ls0=0.f, ls1=0.f;
    #pragma unroll
    for (int nn=0;nn<4;nn++){
      float p00 = exp2f(c[nn][0]-mn0);
      float p01 = exp2f(c[nn][1]-mn0);
      float p10 = exp2f(c[nn][2]-mn1);
      float p11 = exp2f(c[nn][3]-mn1);
      ls0 += p00+p01; ls1 += p10+p11;
      *(float2*)&bP[r0*36 + 8*nn+2*tg] =
        make_float2(__uint_as_float(cvt_tf32(p00)), __uint_as_float(cvt_tf32(p01)));
      *(float2*)&bP[r1*36 + 8*nn+2*tg] =
        make_float2(__uint_as_float(cvt_tf32(p10)), __uint_as_float(cvt_tf32(p11)));
    }
    ls0 += __shfl_xor_sync(~0u,ls0,1); ls0 += __shfl_xor_sync(~0u,ls0,2);
    ls1 += __shfl_xor_sync(~0u,ls1,1); ls1 += __shfl_xor_sync(~0u,ls1,2);
    l0 = l0*a0 + ls0; l1 = l1*a1 + ls1; m0 = mn0; m1 = mn1;
    #pragma unroll
    for (int nn=0;nn<3;nn++){
      o[nn][0]*=a0; o[nn][1]*=a0; o[nn][2]*=a1; o[nn][3]*=a1;
    }
    __syncwarp();   // P rows warp-private; order STS before LDS

    // O += P.V  (V B-frag pairs via one LDS.64 each)
    const unsigned* sPu = (const unsigned*)bP;
    #pragma unroll
    for (int j=0;j<4;j++){
      unsigned a[4];
      a[0] = sPu[r0*36 + 8*j+tg];
      a[1] = sPu[r1*36 + 8*j+tg];
      a[2] = sPu[r0*36 + 8*j+tg+4];
      a[3] = sPu[r1*36 + 8*j+tg+4];
      #pragma unroll
      for (int nn=0;nn<3;nn++){
        uint2 vv = *(const uint2*)&bV[(j*4+tg)*56 + (8*nn+g)*2];
        mma_tf32(o[nn], a, vv.x, vv.y);
      }
    }
  }

  // ---- final merge of the two key-halves (exact flash merge) ----
  __syncthreads();
  int slot = t128*16;
  if (grp==1){
    smf[slot+0]=m0; smf[slot+1]=l0; smf[slot+2]=m1; smf[slot+3]=l1;
    #pragma unroll
    for (int nn=0;nn<3;nn++)
      #pragma unroll
      for (int i=0;i<4;i++) smf[slot+4+nn*4+i] = o[nn][i];
  }
  __syncthreads();
  if (grp==0){
    float mB0=smf[slot+0], lB0=smf[slot+1], mB1=smf[slot+2], lB1=smf[slot+3];
    float mx0 = fmaxf(m0, mB0), mx1 = fmaxf(m1, mB1);
    float sA0 = exp2f(m0-mx0), sB0 = exp2f(mB0-mx0);
    float sA1 = exp2f(m1-mx1), sB1 = exp2f(mB1-mx1);
    float il0 = 1.f/(l0*sA0 + lB0*sB0);
    float il1 = 1.f/(l1*sA1 + lB1*sB1);
    int n0g = q0 + r0, n1g = q0 + r1;
    #pragma unroll
    for (int nn=0;nn<3;nn++){
      int col = h*DD + 8*nn + 2*tg;
      float2 gt0 = *(const float2*)&g_gate[n0g*CC + col];
      float2 gt1 = *(const float2*)&g_gate[n1g*CC + col];
      float y[4];
      y[0] = (o[nn][0]*sA0 + smf[slot+4+nn*4+0]*sB0)*il0*gt0.x;
      y[1] = (o[nn][1]*sA0 + smf[slot+4+nn*4+1]*sB0)*il0*gt0.y;
      y[2] = (o[nn][2]*sA1 + smf[slot+4+nn*4+2]*sB1)*il1*gt1.x;
      y[3] = (o[nn][3]*sA1 + smf[slot+4+nn*4+3]*sB1)*il1*gt1.y;
      int idx[4] = { n0g*CC+col, n0g*CC+col+1, n1g*CC+col, n1g*CC+col+1 };
      #pragma unroll
      for (int i=0;i<4;i++){
        unsigned hx = cvt_tf32(y[i]);
        g_gatedh[idx[i]] = hx;
        g_gatedl[idx[i]] = cvt_tf32(y[i] - __uint_as_float(hx));
      }
    }
  }
}

// ---------------------------------------------------------------------------
// Output projection: out = gated @ wo.T  (3xTF32, pipelined)
// ---------------------------------------------------------------------------
__global__ __launch_bounds__(256) void out_kernel(float* __restrict__ out) {
  extern __shared__ unsigned smu[];
  int c0 = blockIdx.x*64, n0 = blockIdx.y*64;
  float acc[4][4] = {};
  gemm_tc(g_gatedh, g_gatedl, g_wh + 4*WSZ, g_wl + 4*WSZ, n0, c0, acc, smu);
  int lane = threadIdx.x&31, w = threadIdx.x>>5;
  int wm = w>>1, wn = w&1;
  int g = lane>>2, tg = lane&3;
  int row0 = n0 + wm*16 + g, row1 = row0 + 8;
  #pragma unroll
  for (int nn=0;nn<4;nn++){
    int col = c0 + wn*32 + 8*nn + 2*tg;
    *(float2*)&out[row0*CC+col] = make_float2(acc[nn][0], acc[nn][1]);
    *(float2*)&out[row1*CC+col] = make_float2(acc[nn][2], acc[nn][3]);
  }
}

// ---------------------------------------------------------------------------
extern "C" void kernel_launch(void* const* d_in, const int* in_sizes, int n_in,
                              void* d_out, int out_size) {
  const float* x    = (const float*)d_in[0];
  const float* mask = (const float*)d_in[1];
  const float* pair = (const float*)d_in[2];
  const float* ln_w = (const float*)d_in[3];
  const float* ln_b = (const float*)d_in[4];
  const float* wq   = (const float*)d_in[5];
  const float* bq   = (const float*)d_in[6];
  const float* wk   = (const float*)d_in[7];
  const float* wv   = (const float*)d_in[8];
  const float* wg   = (const float*)d_in[9];
  const float* wo   = (const float*)d_in[10];
  float* out = (float*)d_out;

  cudaFuncSetAttribute(proj_kernel, cudaFuncAttributeMaxDynamicSharedMemorySize, 73728);
  cudaFuncSetAttribute(out_kernel,  cudaFuncAttributeMaxDynamicSharedMemorySize, 73728);
  cudaFuncSetAttribute(attn_kernel, cudaFuncAttributeMaxDynamicSharedMemorySize, 65536);

  ln_kernel<<<NN,128>>>(x,mask,ln_w,ln_b);
  wconv_kernel<<<dim3(WSZ/256,5),256>>>(wq,wk,wv,wg,wo);
  proj_kernel<<<dim3(6,32,4),256,73728>>>(bq);
  attn_kernel<<<dim3(32,16),256,65536>>>(pair);
  out_kernel<<<dim3(6,32),256,73728>>>(out);
}

// round 14
// speedup vs baseline: 1.1964x; 1.1964x over previous
#include <cuda_runtime.h>
#include <math.h>

#define NN 2048
#define CC 384
#define HH 16
#define DD 24
#define L2E 1.44269504088896340736f
#define WSZ (CC*CC)

// Scratch (allocation-free rule: __device__ globals)
__device__ unsigned g_xnh[NN*CC], g_xnl[NN*CC];      // tf32 hi/lo of layernormed x
__device__ unsigned g_wh[5*WSZ], g_wl[5*WSZ];        // tf32 hi/lo of wq,wk,wv,wg,wo
__device__ unsigned g_q[NN*CC];                      // [H][N][D], *D^-0.5*log2e, tf32
// K pair-interleaved: [H][12 rows=(4*jd+t)][2N]: (key n, e) = K[d=8jd+t+4e][key n]
__device__ unsigned g_kT2[CC*NN];
// V adjacent-key-pair packed: [H][64 tiles][16 rows][48]:
//   key5=key&31, e=key5&1, m=key5>>1, row=4*(m&3)+(m>>2), col=2*d+e
__device__ unsigned g_v2[CC*NN];
__device__ float    g_gate[NN*CC];                   // sigmoid(xn@wg.T), [N][C]
__device__ unsigned g_gatedh[NN*CC], g_gatedl[NN*CC];// tf32 hi/lo of wa*gate
__device__ float    g_biask[NN];                     // 1e9*(mask-1)*log2e

// ---------------------------------------------------------------------------
__device__ __forceinline__ unsigned cvt_tf32(float x){
  unsigned r; asm("cvt.rna.tf32.f32 %0, %1;" : "=r"(r) : "f"(x)); return r;
}
__device__ __forceinline__ void mma_tf32(float c[4], const unsigned a[4],
                                         unsigned b0, unsigned b1){
  asm volatile("mma.sync.aligned.m16n8k8.row.col.f32.tf32.tf32.f32 "
    "{%0,%1,%2,%3}, {%4,%5,%6,%7}, {%8,%9}, {%0,%1,%2,%3};"
    : "+f"(c[0]),"+f"(c[1]),"+f"(c[2]),"+f"(c[3])
    : "r"(a[0]),"r"(a[1]),"r"(a[2]),"r"(a[3]), "r"(b0),"r"(b1));
}
__device__ __forceinline__ void cp16(void* dst, const void* src){
  unsigned d = (unsigned)__cvta_generic_to_shared(dst);
  asm volatile("cp.async.cg.shared.global [%0], [%1], 16;\n" :: "r"(d), "l"(src));
}
__device__ __forceinline__ void cp_commit(){ asm volatile("cp.async.commit_group;\n"::); }
__device__ __forceinline__ void cp_wait0(){ asm volatile("cp.async.wait_group 0;\n"::); }
__device__ __forceinline__ void cp_wait1(){ asm volatile("cp.async.wait_group 1;\n"::); }

// ---------------------------------------------------------------------------
// LayerNorm -> tf32 hi/lo; also key bias (log2 domain).
// ---------------------------------------------------------------------------
__global__ __launch_bounds__(128) void ln_kernel(
    const float* __restrict__ x, const float* __restrict__ mask,
    const float* __restrict__ ln_w, const float* __restrict__ ln_b) {
  int row = blockIdx.x, tid = threadIdx.x;
  const float* xr = x + row*CC;
  float v[3]; float s = 0.f;
  #pragma unroll
  for (int i=0;i<3;i++){ v[i]=xr[tid+128*i]; s+=v[i]; }
  __shared__ float red[4];
  #pragma unroll
  for (int o=16;o;o>>=1) s += __shfl_xor_sync(~0u,s,o);
  if ((tid&31)==0) red[tid>>5]=s;
  __syncthreads();
  float mu = (red[0]+red[1]+red[2]+red[3])*(1.f/CC);
  __syncthreads();
  float sq=0.f;
  #pragma unroll
  for (int i=0;i<3;i++){ float d=v[i]-mu; sq+=d*d; }
  #pragma unroll
  for (int o=16;o;o>>=1) sq += __shfl_xor_sync(~0u,sq,o);
  if ((tid&31)==0) red[tid>>5]=sq;
  __syncthreads();
  float var = (red[0]+red[1]+red[2]+red[3])*(1.f/CC);
  float rs = rsqrtf(var + 1e-5f);
  #pragma unroll
  for (int i=0;i<3;i++){
    int c = tid+128*i;
    float y = (v[i]-mu)*rs*ln_w[c] + ln_b[c];
    unsigned h = cvt_tf32(y);
    g_xnh[row*CC+c] = h;
    g_xnl[row*CC+c] = cvt_tf32(y - __uint_as_float(h));
  }
  if (tid==0) g_biask[row] = 1e9f*(mask[row]-1.f)*L2E;
}

// ---------------------------------------------------------------------------
// Split the 5 weight matrices into tf32 hi/lo (order: q,k,v,g,o).
// ---------------------------------------------------------------------------
__global__ __launch_bounds__(256) void wconv_kernel(
    const float* __restrict__ wq, const float* __restrict__ wk,
    const float* __restrict__ wv, const float* __restrict__ wg,
    const float* __restrict__ wo) {
  int which = blockIdx.y;
  const float* w = (which==0)?wq:(which==1)?wk:(which==2)?wv:(which==3)?wg:wo;
  int i = blockIdx.x*256 + threadIdx.x;
  float v = w[i];
  unsigned h = cvt_tf32(v);
  g_wh[which*WSZ + i] = h;
  g_wl[which*WSZ + i] = cvt_tf32(v - __uint_as_float(h));
}

// ---------------------------------------------------------------------------
// 3xTF32 tensor-core GEMM, 64x64 tile, K=384, cp.async double-buffered.
// ---------------------------------------------------------------------------
__device__ __forceinline__ void gemm_tc(const unsigned* __restrict__ pAh,
                                        const unsigned* __restrict__ pAl,
                                        const unsigned* __restrict__ pBh,
                                        const unsigned* __restrict__ pBl,
                                        int n0, int c0, float acc[4][4],
                                        unsigned* sm) {
  int tid = threadIdx.x;
  int lane = tid&31, w = tid>>5;
  int wm = w>>1, wn = w&1;
  int g = lane>>2, tg = lane&3;
  int r0 = wm*16 + g, r1 = r0 + 8;

  auto stage = [&](int kt, int b){
    int k0 = kt*32;
    unsigned* base = sm + b*9216;
    #pragma unroll
    for (int i=0;i<8;i++){
      int f = tid + i*256;                 // 0..2047 16B chunks
      int a = f>>9, rr = (f&511)>>3, c4 = (f&7)*4;
      const unsigned* src =
        (a==0) ? &pAh[(n0+rr)*CC + k0 + c4] :
        (a==1) ? &pAl[(n0+rr)*CC + k0 + c4] :
        (a==2) ? &pBh[(c0+rr)*CC + k0 + c4] :
                 &pBl[(c0+rr)*CC + k0 + c4];
      cp16(base + a*2304 + rr*36 + c4, src);
    }
    cp_commit();
  };

  stage(0, 0);
  for (int kt=0; kt<12; kt++){
    int b = kt&1;
    cp_wait0();
    __syncthreads();
    if (kt < 11) stage(kt+1, b^1);
    const unsigned* Ah = sm + b*9216;
    const unsigned* Al = Ah + 2304;
    const unsigned* Bh = Al + 2304;
    const unsigned* Bl = Bh + 2304;
    #pragma unroll
    for (int ks=0; ks<4; ks++){
      int k = ks*8;
      unsigned ah[4], al[4];
      ah[0]=Ah[r0*36+k+tg]; ah[1]=Ah[r1*36+k+tg];
      ah[2]=Ah[r0*36+k+tg+4]; ah[3]=Ah[r1*36+k+tg+4];
      al[0]=Al[r0*36+k+tg]; al[1]=Al[r1*36+k+tg];
      al[2]=Al[r0*36+k+tg+4]; al[3]=Al[r1*36+k+tg+4];
      #pragma unroll
      for (int nn=0; nn<4; nn++){
        int col = wn*32 + 8*nn + g;
        unsigned bh0=Bh[col*36+k+tg], bh1=Bh[col*36+k+tg+4];
        unsigned bl0=Bl[col*36+k+tg], bl1=Bl[col*36+k+tg+4];
        mma_tf32(acc[nn], ah, bh0, bh1);
        mma_tf32(acc[nn], al, bh0, bh1);
        mma_tf32(acc[nn], ah, bl0, bl1);
      }
    }
  }
}

// ---------------------------------------------------------------------------
// All four projections (blockIdx.z selects q/k/v/g).
// q tf32 [H][N][D]; K d-pair-interleaved; V adjacent-key-pair packed.
// ---------------------------------------------------------------------------
__device__ __forceinline__ void proj_store(int proj, int row, int col, float val,
                                           const float* __restrict__ bq){
  if (proj==0){
    val = (val + bq[col]) * (0.2041241452f * L2E);   // D^-0.5 * log2e
    g_q[(col/DD)*NN*DD + row*DD + (col%DD)] = cvt_tf32(val);
  } else if (proj==1){
    int h = col/DD, dd = col%DD;
    int j = dd>>3, rem = dd&7, e = rem>>2, t = rem&3;
    g_kT2[h*24*NN + (j*4+t)*2*NN + 2*row + e] = cvt_tf32(val);
  } else if (proj==2){
    int h = col/DD, d = col%DD;
    int T = row>>5, key5 = row&31;
    int e = key5&1, m = key5>>1;
    int vrow = 4*(m&3) + (m>>2);
    g_v2[((h*64 + T)*16 + vrow)*48 + d*2 + e] = cvt_tf32(val);
  } else {
    g_gate[row*CC+col] = 1.f/(1.f+__expf(-val));
  }
}

__global__ __launch_bounds__(256) void proj_kernel(const float* __restrict__ bq) {
  extern __shared__ unsigned smu[];
  int proj = blockIdx.z;
  int c0 = blockIdx.x*64, n0 = blockIdx.y*64;
  float acc[4][4] = {};
  gemm_tc(g_xnh, g_xnl, g_wh + proj*WSZ, g_wl + proj*WSZ, n0, c0, acc, smu);
  int lane = threadIdx.x&31, w = threadIdx.x>>5;
  int wm = w>>1, wn = w&1;
  int g = lane>>2, tg = lane&3;
  int row0 = n0 + wm*16 + g, row1 = row0 + 8;
  #pragma unroll
  for (int nn=0;nn<4;nn++){
    int col = c0 + wn*32 + 8*nn + 2*tg;
    proj_store(proj, row0, col,   acc[nn][0], bq);
    proj_store(proj, row0, col+1, acc[nn][1], bq);
    proj_store(proj, row1, col,   acc[nn][2], bq);
    proj_store(proj, row1, col+1, acc[nn][3], bq);
  }
}

// ---------------------------------------------------------------------------
// Tensor-core flash attention, 32-key tiles, 3-stage cp.async pipeline,
// KEY-PERMUTED so P never leaves registers (C-frag == A-frag):
//   QK n-slot (nn,g) <- gmem key G = 8*(g>>1) + 2*nn + (g&1)
//   => C-init reads pair cols [8tg..8tg+7] contiguously (2x LDS.128)
//   => PV A-frags are P's own C registers; V packed by adjacent key pairs.
// Dynamic smem 49152B = 3 stages x 4096 floats:
//   [0,2304)    pair (stride 36)
//   [2304,3120) K (12 rows x 68, LDS.64 B-frags, conflict-free)
//   [3120,4016) V (16 rows x 56, LDS.64 B-frags, conflict-free)
// ---------------------------------------------------------------------------
__global__ __launch_bounds__(128) void attn_kernel(const float* __restrict__ pair) {
  extern __shared__ float smf[];
  unsigned* smu = (unsigned*)smf;

  int h = blockIdx.y, q0 = blockIdx.x*64;
  int tid = threadIdx.x;
  int w = tid>>5, lane = tid&31;
  int g = lane>>2, tg = lane&3;
  int r0 = 16*w + g, r1 = r0 + 8;
  bool lo64 = (tid < 64);
  int kcol0 = 16*(g>>1) + 2*(g&1);        // per-thread K column base (x2 words)

  // ---- fixed staging slots (computed once) ----
  const float* pb = pair + (size_t)h*NN*NN + (size_t)q0*NN;
  const float* psrc[4]; int pdst[4];
  #pragma unroll
  for (int i=0;i<4;i++){
    int f = tid + 128*i;                   // 512 chunks: 64 rows x 8
    int r = f>>3, c4 = (f&7)*4;
    psrc[i] = pb + (size_t)r*NN + c4;
    pdst[i] = r*36 + c4;
  }
  const unsigned* kTb2 = g_kT2 + h*24*NN;
  int kr0 = tid>>4,       kq0 = tid&15;
  int kr1 = (tid+128)>>4, kq1 = (tid+128)&15;   // rows 8..11, tid<64 only
  const unsigned* ks0 = kTb2 + kr0*2*NN + kq0*4;
  const unsigned* ks1 = kTb2 + kr1*2*NN + kq1*4;
  int kd0 = kr0*68 + kq0*4, kd1 = kr1*68 + kq1*4;

  const unsigned* vb2 = g_v2 + h*64*768;
  int vr0 = tid/12,       vq0 = tid - vr0*12;
  int vr1 = (tid+128)/12, vq1 = (tid+128) - vr1*12;  // tid<64 only
  const unsigned* vs0 = vb2 + vr0*48 + vq0*4;
  const unsigned* vs1 = vb2 + vr1*48 + vq1*4;
  int vd0 = vr0*56 + vq0*4, vd1 = vr1*56 + vq1*4;

  auto stage = [&](int t, int s){
    float*    pairb = smf + s*4096;
    unsigned* Kb    = smu + s*4096 + 2304;
    unsigned* Vb    = smu + s*4096 + 3120;
    int koff = t*32;
    #pragma unroll
    for (int i=0;i<4;i++) cp16(pairb + pdst[i], psrc[i] + koff);
    cp16(Kb + kd0, ks0 + koff*2);
    if (lo64) cp16(Kb + kd1, ks1 + koff*2);
    cp16(Vb + vd0, vs0 + t*768);
    if (lo64) cp16(Vb + vd1, vs1 + t*768);
    cp_commit();
  };

  // Q A-frags in registers (pre-converted tf32)
  unsigned qa[3][4];
  {
    const unsigned* qb = &g_q[(size_t)h*NN*DD + (size_t)q0*DD];
    #pragma unroll
    for (int j=0;j<3;j++){
      qa[j][0] = qb[r0*DD + 8*j+tg];
      qa[j][1] = qb[r1*DD + 8*j+tg];
      qa[j][2] = qb[r0*DD + 8*j+tg+4];
      qa[j][3] = qb[r1*DD + 8*j+tg+4];
    }
  }
  float m0=-1e30f, m1=-1e30f, l0=0.f, l1=0.f;
  float o[3][4] = {};

  stage(0, 0);
  stage(1, 1);
  int s = 0;
  for (int t=0;t<64;t++){
    int k0 = t*32;
    if (t < 63) cp_wait1(); else cp_wait0();
    __syncthreads();
    if (t < 62) stage(t+2, (t+2) % 3);

    const float*    bP = smf + s*4096;
    const unsigned* bK = smu + s*4096 + 2304;
    const unsigned* bV = smu + s*4096 + 3120;

    // C := pair*log2e + bias (fp32 exact); contiguous 8-col reads per row
    float4 xa0 = *(const float4*)&bP[r0*36 + 8*tg];
    float4 xa1 = *(const float4*)&bP[r0*36 + 8*tg + 4];
    float4 xb0 = *(const float4*)&bP[r1*36 + 8*tg];
    float4 xb1 = *(const float4*)&bP[r1*36 + 8*tg + 4];
    float4 bb0 = *(const float4*)&g_biask[k0 + 8*tg];
    float4 bb1 = *(const float4*)&g_biask[k0 + 8*tg + 4];
    float c[4][4];
    c[0][0]=fmaf(xa0.x,L2E,bb0.x); c[0][1]=fmaf(xa0.y,L2E,bb0.y);
    c[1][0]=fmaf(xa0.z,L2E,bb0.z); c[1][1]=fmaf(xa0.w,L2E,bb0.w);
    c[2][0]=fmaf(xa1.x,L2E,bb1.x); c[2][1]=fmaf(xa1.y,L2E,bb1.y);
    c[3][0]=fmaf(xa1.z,L2E,bb1.z); c[3][1]=fmaf(xa1.w,L2E,bb1.w);
    c[0][2]=fmaf(xb0.x,L2E,bb0.x); c[0][3]=fmaf(xb0.y,L2E,bb0.y);
    c[1][2]=fmaf(xb0.z,L2E,bb0.z); c[1][3]=fmaf(xb0.w,L2E,bb0.w);
    c[2][2]=fmaf(xb1.x,L2E,bb1.x); c[2][3]=fmaf(xb1.y,L2E,bb1.y);
    c[3][2]=fmaf(xb1.z,L2E,bb1.z); c[3][3]=fmaf(xb1.w,L2E,bb1.w);

    // S += Q.K^T  (permuted key columns: 4nn + kcol0)
    #pragma unroll
    for (int j=0;j<3;j++){
      #pragma unroll
      for (int nn=0;nn<4;nn++){
        uint2 kk = *(const uint2*)&bK[(j*4+tg)*68 + 4*nn + kcol0];
        mma_tf32(c[nn], qa[j], kk.x, kk.y);
      }
    }

    // online softmax (log2 domain); P stays in registers
    float rm0=-1e30f, rm1=-1e30f;
    #pragma unroll
    for (int nn=0;nn<4;nn++){
      rm0 = fmaxf(rm0, fmaxf(c[nn][0], c[nn][1]));
      rm1 = fmaxf(rm1, fmaxf(c[nn][2], c[nn][3]));
    }
    rm0 = fmaxf(rm0, __shfl_xor_sync(~0u,rm0,1));
    rm0 = fmaxf(rm0, __shfl_xor_sync(~0u,rm0,2));
    rm1 = fmaxf(rm1, __shfl_xor_sync(~0u,rm1,1));
    rm1 = fmaxf(rm1, __shfl_xor_sync(~0u,rm1,2));
    float mn0 = fmaxf(m0, rm0), mn1 = fmaxf(m1, rm1);
    float a0 = exp2f(m0-mn0), a1 = exp2f(m1-mn1);
    float ls0=0.f, ls1=0.f;
    unsigned pa[4][4];                     // A-frags for PV, direct from P
    #pragma unroll
    for (int nn=0;nn<4;nn++){
      float p00 = exp2f(c[nn][0]-mn0);     // r0, e=0
      float p01 = exp2f(c[nn][1]-mn0);     // r0, e=1
      float p10 = exp2f(c[nn][2]-mn1);     // r1, e=0
      float p11 = exp2f(c[nn][3]-mn1);     // r1, e=1
      ls0 += p00+p01; ls1 += p10+p11;
      pa[nn][0] = cvt_tf32(p00);           // A[r0][k=tg]
      pa[nn][1] = cvt_tf32(p10);           // A[r1][k=tg]
      pa[nn][2] = cvt_tf32(p01);           // A[r0][k=tg+4]
      pa[nn][3] = cvt_tf32(p11);           // A[r1][k=tg+4]
    }
    ls0 += __shfl_xor_sync(~0u,ls0,1); ls0 += __shfl_xor_sync(~0u,ls0,2);
    ls1 += __shfl_xor_sync(~0u,ls1,1); ls1 += __shfl_xor_sync(~0u,ls1,2);
    l0 = l0*a0 + ls0; l1 = l1*a1 + ls1; m0 = mn0; m1 = mn1;
    #pragma unroll
    for (int nn=0;nn<3;nn++){
      o[nn][0]*=a0; o[nn][1]*=a0; o[nn][2]*=a1; o[nn][3]*=a1;
    }

    // O += P.V  (V packed so k-group j pairs adjacent gmem keys)
    #pragma unroll
    for (int j=0;j<4;j++){
      #pragma unroll
      for (int nn=0;nn<3;nn++){
        uint2 vv = *(const uint2*)&bV[(j*4+tg)*56 + (8*nn+g)*2];
        mma_tf32(o[nn], pa[j], vv.x, vv.y);
      }
    }
    s++; if (s==3) s = 0;
  }

  // epilogue: normalize + gate -> hi/lo for the output GEMM
  float il0 = 1.f/l0, il1 = 1.f/l1;
  int n0g = q0 + r0, n1g = q0 + r1;
  #pragma unroll
  for (int nn=0;nn<3;nn++){
    int col = h*DD + 8*nn + 2*tg;
    float2 gt0 = *(const float2*)&g_gate[n0g*CC + col];
    float2 gt1 = *(const float2*)&g_gate[n1g*CC + col];
    float y[4] = { o[nn][0]*il0*gt0.x, o[nn][1]*il0*gt0.y,
                   o[nn][2]*il1*gt1.x, o[nn][3]*il1*gt1.y };
    int idx[4] = { n0g*CC+col, n0g*CC+col+1, n1g*CC+col, n1g*CC+col+1 };
    #pragma unroll
    for (int i=0;i<4;i++){
      unsigned hx = cvt_tf32(y[i]);
      g_gatedh[idx[i]] = hx;
      g_gatedl[idx[i]] = cvt_tf32(y[i] - __uint_as_float(hx));
    }
  }
}

// ---------------------------------------------------------------------------
// Output projection: out = gated @ wo.T  (3xTF32, pipelined)
// ---------------------------------------------------------------------------
__global__ __launch_bounds__(256) void out_kernel(float* __restrict__ out) {
  extern __shared__ unsigned smu[];
  int c0 = blockIdx.x*64, n0 = blockIdx.y*64;
  float acc[4][4] = {};
  gemm_tc(g_gatedh, g_gatedl, g_wh + 4*WSZ, g_wl + 4*WSZ, n0, c0, acc, smu);
  int lane = threadIdx.x&31, w = threadIdx.x>>5;
  int wm = w>>1, wn = w&1;
  int g = lane>>2, tg = lane&3;
  int row0 = n0 + wm*16 + g, row1 = row0 + 8;
  #pragma unroll
  for (int nn=0;nn<4;nn++){
    int col = c0 + wn*32 + 8*nn + 2*tg;
    *(float2*)&out[row0*CC+col] = make_float2(acc[nn][0], acc[nn][1]);
    *(float2*)&out[row1*CC+col] = make_float2(acc[nn][2], acc[nn][3]);
  }
}

// ---------------------------------------------------------------------------
extern "C" void kernel_launch(void* const* d_in, const int* in_sizes, int n_in,
                              void* d_out, int out_size) {
  const float* x    = (const float*)d_in[0];
  const float* mask = (const float*)d_in[1];
  const float* pair = (const float*)d_in[2];
  const float* ln_w = (const float*)d_in[3];
  const float* ln_b = (const float*)d_in[4];
  const float* wq   = (const float*)d_in[5];
  const float* bq   = (const float*)d_in[6];
  const float* wk   = (const float*)d_in[7];
  const float* wv   = (const float*)d_in[8];
  const float* wg   = (const float*)d_in[9];
  const float* wo   = (const float*)d_in[10];
  float* out = (float*)d_out;

  cudaFuncSetAttribute(proj_kernel, cudaFuncAttributeMaxDynamicSharedMemorySize, 73728);
  cudaFuncSetAttribute(out_kernel,  cudaFuncAttributeMaxDynamicSharedMemorySize, 73728);
  cudaFuncSetAttribute(attn_kernel, cudaFuncAttributeMaxDynamicSharedMemorySize, 49152);

  ln_kernel<<<NN,128>>>(x,mask,ln_w,ln_b);
  wconv_kernel<<<dim3(WSZ/256,5),256>>>(wq,wk,wv,wg,wo);
  proj_kernel<<<dim3(6,32,4),256,73728>>>(bq);
  attn_kernel<<<dim3(32,16),128,49152>>>(pair);
  out_kernel<<<dim3(6,32),256,73728>>>(out);
}